// round 3
// baseline (speedup 1.0000x reference)
#include <cuda_runtime.h>

#define NMAX 100000
#define DD 128

// Static device scratch (allocation-free). Referenced only from device code.
__device__ float g_bufA[NMAX * DD];
__device__ float g_bufB[NMAX * DD];
__device__ float g_dinv[NMAX];
__device__ int   g_is64;

__device__ __forceinline__ float lrelu(float v) { return v > 0.0f ? v : 0.01f * v; }

// Edge index fetch robust to int32-vs-int64 delivery of edge_index.
__device__ __forceinline__ int edge_at(const void* eidx, long long pos) {
    if (g_is64) return (int)(((const long long*)eidx)[pos]);
    return ((const int*)eidx)[pos];
}

// ---------------- dtype sniff ----------------
// int64 LE read as int32 looks like [v,0,v,0,...]; genuine int32 has nonzero odd slots.
__global__ void sniff_dtype(const int* __restrict__ p, int n) {
    if (threadIdx.x == 0 && blockIdx.x == 0) {
        int is64 = 1;
        for (int i = 0; i < 64; i++) {
            int lo = p[2 * i], hi = p[2 * i + 1];
            if (hi != 0 || lo < 0 || lo >= n) { is64 = 0; break; }
        }
        g_is64 = is64;
    }
}

// ---------------- degree / normalization ----------------
__global__ void deg_init(int n) {
    int i = blockIdx.x * blockDim.x + threadIdx.x;
    if (i < n) g_dinv[i] = 1.0f;  // self-loop
}

__global__ void deg_count(const void* __restrict__ eidx, int ne) {
    int e = blockIdx.x * blockDim.x + threadIdx.x;
    if (e < ne) atomicAdd(&g_dinv[edge_at(eidx, (long long)ne + e)], 1.0f);
}

__global__ void deg_finish(int n) {
    int i = blockIdx.x * blockDim.x + threadIdx.x;
    if (i < n) g_dinv[i] = rsqrtf(g_dinv[i]);
}

// ---------------- fused feature kernel ----------------
// 4 nodes per block, 128 threads. Writes x1 = lrelu(x0@Win+bin) into g_bufA.
__global__ void __launch_bounds__(128) kfeat(
    const float* __restrict__ des, const float* __restrict__ tweet,
    const float* __restrict__ nump, const float* __restrict__ catp,
    const float* __restrict__ Wd, const float* __restrict__ bd,
    const float* __restrict__ Wt, const float* __restrict__ bt,
    const float* __restrict__ Wn, const float* __restrict__ bn,
    const float* __restrict__ Wc, const float* __restrict__ bc,
    const float* __restrict__ Win, const float* __restrict__ bin, int n)
{
    __shared__ float sdes[4][768];
    __shared__ float stw[4][768];
    __shared__ float ps[128][4];
    __shared__ float x0[4][128];

    int t = threadIdx.x;
    int node0 = blockIdx.x * 4;

    for (int m = 0; m < 4; m++) {
        int node = node0 + m;
        if (node < n) {
            const float* dp = des + (size_t)node * 768;
            const float* tp = tweet + (size_t)node * 768;
            for (int k = t; k < 768; k += 128) { sdes[m][k] = dp[k]; stw[m][k] = tp[k]; }
        } else {
            for (int k = t; k < 768; k += 128) { sdes[m][k] = 0.0f; stw[m][k] = 0.0f; }
        }
    }
    __syncthreads();

    // heavy partial dot-products: 64 columns (32 des + 32 tweet), k split in halves
    {
        int c = t & 63;
        int k0 = (t >> 6) * 384;
        float a0 = 0.f, a1 = 0.f, a2 = 0.f, a3 = 0.f;
        if (c < 32) {
            const float* Wp = Wd + c;
            #pragma unroll 4
            for (int k = k0; k < k0 + 384; k++) {
                float wk = Wp[k * 32];
                a0 += sdes[0][k] * wk; a1 += sdes[1][k] * wk;
                a2 += sdes[2][k] * wk; a3 += sdes[3][k] * wk;
            }
        } else {
            const float* Wp = Wt + (c - 32);
            #pragma unroll 4
            for (int k = k0; k < k0 + 384; k++) {
                float wk = Wp[k * 32];
                a0 += stw[0][k] * wk; a1 += stw[1][k] * wk;
                a2 += stw[2][k] * wk; a3 += stw[3][k] * wk;
            }
        }
        ps[t][0] = a0; ps[t][1] = a1; ps[t][2] = a2; ps[t][3] = a3;
    }
    __syncthreads();

    if (t < 64) {
        int c = t;
        float bias = (c < 32) ? bd[c] : bt[c - 32];
        #pragma unroll
        for (int m = 0; m < 4; m++) {
            float v = ps[c][m] + ps[c + 64][m] + bias;
            x0[m][c] = lrelu(v);
        }
    } else {
        int c = t - 64;
        if (c < 32) {
            #pragma unroll
            for (int m = 0; m < 4; m++) {
                int node = node0 + m;
                float v = bn[c];
                if (node < n) {
                    const float* xp = nump + (size_t)node * 6;
                    #pragma unroll
                    for (int k = 0; k < 6; k++) v += xp[k] * Wn[k * 32 + c];
                }
                x0[m][64 + c] = lrelu(v);
            }
        } else {
            int cc = c - 32;
            #pragma unroll
            for (int m = 0; m < 4; m++) {
                int node = node0 + m;
                float v = bc[cc];
                if (node < n) {
                    const float* xp = catp + (size_t)node * 11;
                    #pragma unroll
                    for (int k = 0; k < 11; k++) v += xp[k] * Wc[k * 32 + cc];
                }
                x0[m][96 + cc] = lrelu(v);
            }
        }
    }
    __syncthreads();

    // x1 = lrelu(x0 @ Win + bin) -> g_bufA
    {
        float b = bin[t];
        float a0 = b, a1 = b, a2 = b, a3 = b;
        const float* Wp = Win + t;
        #pragma unroll 4
        for (int k = 0; k < 128; k++) {
            float wk = Wp[k * 128];
            a0 += x0[0][k] * wk; a1 += x0[1][k] * wk;
            a2 += x0[2][k] * wk; a3 += x0[3][k] * wk;
        }
        float acc[4] = {a0, a1, a2, a3};
        #pragma unroll
        for (int m = 0; m < 4; m++) {
            int node = node0 + m;
            if (node < n) g_bufA[(size_t)node * 128 + t] = acc[m] > 0.f ? acc[m] : 0.01f * acc[m];
        }
    }
}

// ---------------- 128x128 GEMM: g_bufA @ W -> g_bufB, 8 nodes/block ----------------
__global__ void __launch_bounds__(128) gemm128(const float* __restrict__ W, int n)
{
    __shared__ float xs[8][128];
    int t = threadIdx.x;
    int node0 = blockIdx.x * 8;
    #pragma unroll
    for (int m = 0; m < 8; m++) {
        int nd = node0 + m;
        xs[m][t] = (nd < n) ? g_bufA[(size_t)nd * 128 + t] : 0.0f;
    }
    __syncthreads();

    float acc[8];
    #pragma unroll
    for (int m = 0; m < 8; m++) acc[m] = 0.0f;
    const float* Wp = W + t;
    #pragma unroll 4
    for (int k = 0; k < 128; k++) {
        float wk = Wp[k * 128];
        #pragma unroll
        for (int m = 0; m < 8; m++) acc[m] += xs[m][k] * wk;
    }
    #pragma unroll
    for (int m = 0; m < 8; m++) {
        int nd = node0 + m;
        if (nd < n) g_bufB[(size_t)nd * 128 + t] = acc[m];
    }
}

// ---------------- aggregation init: self loop + bias (g_bufB -> g_bufA) ----------------
__global__ void agg_init(const float* __restrict__ bias, int n)
{
    int i = blockIdx.x * blockDim.x + threadIdx.x;
    if (i >= n * DD) return;
    int node = i >> 7;
    int j = i & 127;
    float di = g_dinv[node];
    g_bufA[i] = di * di * g_bufB[i] + bias[j];
}

// ---------------- edge scatter-add: g_bufB[src] -> g_bufA[dst], 1 warp/edge ----------------
__global__ void __launch_bounds__(256) scatter(const void* __restrict__ eidx, int ne)
{
    long long gid = (long long)blockIdx.x * blockDim.x + threadIdx.x;
    int e = (int)(gid >> 5);
    int lane = (int)(gid & 31);
    if (e >= ne) return;
    int s = edge_at(eidx, e);
    int d = edge_at(eidx, (long long)ne + e);
    float w = g_dinv[s] * g_dinv[d];
    const float* ys = g_bufB + (size_t)s * 128;
    float* ad = g_bufA + (size_t)d * 128;
    #pragma unroll
    for (int j = lane; j < 128; j += 32) atomicAdd(&ad[j], w * ys[j]);
}

// ---------------- output head: lrelu(g_bufA@Wo1+bo1) @ Wo2 + bo2 ----------------
__global__ void __launch_bounds__(128) kout(
    const float* __restrict__ Wo1, const float* __restrict__ bo1,
    const float* __restrict__ Wo2, const float* __restrict__ bo2,
    float* __restrict__ out, int n)
{
    __shared__ float xs[128];
    __shared__ float red[8];
    int t = threadIdx.x;
    int node = blockIdx.x;
    xs[t] = g_bufA[(size_t)node * 128 + t];
    __syncthreads();

    float a = bo1[t];
    const float* Wp = Wo1 + t;
    #pragma unroll 4
    for (int k = 0; k < 128; k++) a += xs[k] * Wp[k * 128];
    a = lrelu(a);

    float p0 = a * Wo2[t * 2 + 0];
    float p1 = a * Wo2[t * 2 + 1];
    #pragma unroll
    for (int o = 16; o > 0; o >>= 1) {
        p0 += __shfl_down_sync(0xffffffffu, p0, o);
        p1 += __shfl_down_sync(0xffffffffu, p1, o);
    }
    if ((t & 31) == 0) { red[t >> 5] = p0; red[4 + (t >> 5)] = p1; }
    __syncthreads();
    if (t == 0) {
        out[(size_t)node * 2 + 0] = red[0] + red[1] + red[2] + red[3] + bo2[0];
        out[(size_t)node * 2 + 1] = red[4] + red[5] + red[6] + red[7] + bo2[1];
    }
}

extern "C" void kernel_launch(void* const* d_in, const int* in_sizes, int n_in,
                              void* d_out, int out_size)
{
    const float* des   = (const float*)d_in[0];
    const float* tweet = (const float*)d_in[1];
    const float* nump  = (const float*)d_in[2];
    const float* catp  = (const float*)d_in[3];
    const void*  eidx  = d_in[4];
    // d_in[5] edge_type: unused by reference
    const float* Wd  = (const float*)d_in[6];  const float* bd  = (const float*)d_in[7];
    const float* Wt  = (const float*)d_in[8];  const float* bt  = (const float*)d_in[9];
    const float* Wn  = (const float*)d_in[10]; const float* bn  = (const float*)d_in[11];
    const float* Wc  = (const float*)d_in[12]; const float* bc  = (const float*)d_in[13];
    const float* Win = (const float*)d_in[14]; const float* bin = (const float*)d_in[15];
    const float* Wg1 = (const float*)d_in[16]; const float* bg1 = (const float*)d_in[17];
    const float* Wg2 = (const float*)d_in[18]; const float* bg2 = (const float*)d_in[19];
    const float* Wo1 = (const float*)d_in[20]; const float* bo1 = (const float*)d_in[21];
    const float* Wo2 = (const float*)d_in[22]; const float* bo2 = (const float*)d_in[23];
    float* out = (float*)d_out;

    int n  = in_sizes[2] / 6;   // num_prop is [N, 6]
    int ne = in_sizes[5];       // edge_type is [E]

    // detect int32 vs int64 edge_index delivery
    sniff_dtype<<<1, 32>>>((const int*)eidx, n);

    // degree + D^-1/2
    deg_init<<<(n + 255) / 256, 256>>>(n);
    deg_count<<<(ne + 255) / 256, 256>>>(eidx, ne);
    deg_finish<<<(n + 255) / 256, 256>>>(n);

    // fused input features + W_in -> g_bufA = x1
    kfeat<<<(n + 3) / 4, 128>>>(des, tweet, nump, catp,
                                Wd, bd, Wt, bt, Wn, bn, Wc, bc, Win, bin, n);

    long long warp_threads = (long long)ne * 32;
    int sc_blocks = (int)((warp_threads + 255) / 256);

    // GCN layer 1
    gemm128<<<(n + 7) / 8, 128>>>(Wg1, n);
    agg_init<<<(n * DD + 255) / 256, 256>>>(bg1, n);
    scatter<<<sc_blocks, 256>>>(eidx, ne);

    // GCN layer 2
    gemm128<<<(n + 7) / 8, 128>>>(Wg2, n);
    agg_init<<<(n * DD + 255) / 256, 256>>>(bg2, n);
    scatter<<<sc_blocks, 256>>>(eidx, ne);

    // output head
    kout<<<n, 128>>>(Wo1, bo1, Wo2, bo2, out, n);
}

// round 4
// speedup vs baseline: 1.8006x; 1.8006x over previous
#include <cuda_runtime.h>

#define NMAX 100000
#define EMAX 3300000
#define DD 128

// Static device scratch (allocation-free). Referenced only from device code.
__device__ float g_bufA[NMAX * DD];
__device__ float g_bufB[NMAX * DD];
__device__ float g_dinv[NMAX];
__device__ int   g_deg[NMAX];
__device__ int   g_fill[NMAX];
__device__ int   g_rowptr[NMAX + 1];
__device__ int   g_bsum[256];
__device__ int   g_bsum2[256];
__device__ int   g_csrsrc[EMAX];
__device__ int   g_is64;

__device__ __forceinline__ float lrelu(float v) { return v > 0.0f ? v : 0.01f * v; }

// Edge index fetch robust to int32-vs-int64 delivery of edge_index.
__device__ __forceinline__ int edge_at(const void* eidx, long long pos) {
    if (g_is64) return (int)(((const long long*)eidx)[pos]);
    return ((const int*)eidx)[pos];
}

// int64 LE read as int32 looks like [v,0,v,0,...]; genuine int32 has nonzero odd slots.
__global__ void sniff_dtype(const int* __restrict__ p, int n) {
    if (threadIdx.x == 0 && blockIdx.x == 0) {
        int is64 = 1;
        for (int i = 0; i < 64; i++) {
            int lo = p[2 * i], hi = p[2 * i + 1];
            if (hi != 0 || lo < 0 || lo >= n) { is64 = 0; break; }
        }
        g_is64 = is64;
    }
}

// ---------------- degree ----------------
__global__ void deg_zero(int n) {
    int i = blockIdx.x * blockDim.x + threadIdx.x;
    if (i < n) { g_deg[i] = 0; g_fill[i] = 0; }
}

__global__ void deg_count(const void* __restrict__ eidx, int ne) {
    int e = blockIdx.x * blockDim.x + threadIdx.x;
    if (e < ne) atomicAdd(&g_deg[edge_at(eidx, (long long)ne + e)], 1);
}

__global__ void deg_finish(int n) {
    int i = blockIdx.x * blockDim.x + threadIdx.x;
    if (i < n) g_dinv[i] = rsqrtf((float)(g_deg[i] + 1));  // +1 self loop
}

// ---------------- exclusive scan of g_deg -> g_rowptr (1024 elems / block) ----------------
__global__ void __launch_bounds__(256) scan1(int n) {
    __shared__ int warpsum[8];
    int t = threadIdx.x;
    int base = blockIdx.x * 1024;
    int i0 = base + t * 4;
    int v0 = (i0 + 0 < n) ? g_deg[i0 + 0] : 0;
    int v1 = (i0 + 1 < n) ? g_deg[i0 + 1] : 0;
    int v2 = (i0 + 2 < n) ? g_deg[i0 + 2] : 0;
    int v3 = (i0 + 3 < n) ? g_deg[i0 + 3] : 0;
    int tsum = v0 + v1 + v2 + v3;
    int x = tsum;
    #pragma unroll
    for (int o = 1; o < 32; o <<= 1) {
        int y = __shfl_up_sync(0xffffffffu, x, o);
        if ((t & 31) >= o) x += y;
    }
    if ((t & 31) == 31) warpsum[t >> 5] = x;
    __syncthreads();
    if (t < 32) {
        int w = (t < 8) ? warpsum[t] : 0;
        int xx = w;
        #pragma unroll
        for (int o = 1; o < 8; o <<= 1) {
            int y = __shfl_up_sync(0xffffffffu, xx, o);
            if (t >= o) xx += y;
        }
        if (t < 8) warpsum[t] = xx - w;  // exclusive warp offsets
    }
    __syncthreads();
    int ex = x - tsum + warpsum[t >> 5];  // exclusive prefix within block
    if (i0 + 0 < n) g_rowptr[i0 + 0] = ex;
    if (i0 + 1 < n) g_rowptr[i0 + 1] = ex + v0;
    if (i0 + 2 < n) g_rowptr[i0 + 2] = ex + v0 + v1;
    if (i0 + 3 < n) g_rowptr[i0 + 3] = ex + v0 + v1 + v2;
    if (t == 255) g_bsum[blockIdx.x] = ex + tsum;  // block total
}

__global__ void __launch_bounds__(128) scan2(int nb) {
    __shared__ int ws[4];
    int t = threadIdx.x;
    int v = (t < nb) ? g_bsum[t] : 0;
    int x = v;
    #pragma unroll
    for (int o = 1; o < 32; o <<= 1) {
        int y = __shfl_up_sync(0xffffffffu, x, o);
        if ((t & 31) >= o) x += y;
    }
    if ((t & 31) == 31) ws[t >> 5] = x;
    __syncthreads();
    if (t < 32) {
        int w = (t < 4) ? ws[t] : 0;
        int xx = w;
        #pragma unroll
        for (int o = 1; o < 4; o <<= 1) {
            int y = __shfl_up_sync(0xffffffffu, xx, o);
            if (t >= o) xx += y;
        }
        if (t < 4) ws[t] = xx - w;
    }
    __syncthreads();
    g_bsum2[t] = x - v + ws[t >> 5];  // exclusive
}

__global__ void __launch_bounds__(256) scan3(int n, int ne) {
    int t = threadIdx.x;
    int add = g_bsum2[blockIdx.x];
    int i0 = blockIdx.x * 1024 + t * 4;
    #pragma unroll
    for (int j = 0; j < 4; j++)
        if (i0 + j < n) g_rowptr[i0 + j] += add;
    if (blockIdx.x == 0 && t == 0) g_rowptr[n] = ne;
}

// ---------------- CSR fill ----------------
__global__ void csr_fill(const void* __restrict__ eidx, int ne) {
    int e = blockIdx.x * blockDim.x + threadIdx.x;
    if (e >= ne) return;
    int s = edge_at(eidx, e);
    int d = edge_at(eidx, (long long)ne + e);
    int pos = g_rowptr[d] + atomicAdd(&g_fill[d], 1);
    g_csrsrc[pos] = s;
}

// ---------------- fused feature kernel ----------------
// 4 nodes per block, 128 threads. Writes x1 = lrelu(x0@Win+bin) into g_bufA.
__global__ void __launch_bounds__(128) kfeat(
    const float* __restrict__ des, const float* __restrict__ tweet,
    const float* __restrict__ nump, const float* __restrict__ catp,
    const float* __restrict__ Wd, const float* __restrict__ bd,
    const float* __restrict__ Wt, const float* __restrict__ bt,
    const float* __restrict__ Wn, const float* __restrict__ bn,
    const float* __restrict__ Wc, const float* __restrict__ bc,
    const float* __restrict__ Win, const float* __restrict__ bin, int n)
{
    __shared__ float sdes[4][768];
    __shared__ float stw[4][768];
    __shared__ float ps[128][4];
    __shared__ float x0[4][128];

    int t = threadIdx.x;
    int node0 = blockIdx.x * 4;

    for (int m = 0; m < 4; m++) {
        int node = node0 + m;
        if (node < n) {
            const float* dp = des + (size_t)node * 768;
            const float* tp = tweet + (size_t)node * 768;
            for (int k = t; k < 768; k += 128) { sdes[m][k] = dp[k]; stw[m][k] = tp[k]; }
        } else {
            for (int k = t; k < 768; k += 128) { sdes[m][k] = 0.0f; stw[m][k] = 0.0f; }
        }
    }
    __syncthreads();

    {
        int c = t & 63;
        int k0 = (t >> 6) * 384;
        float a0 = 0.f, a1 = 0.f, a2 = 0.f, a3 = 0.f;
        if (c < 32) {
            const float* Wp = Wd + c;
            #pragma unroll 4
            for (int k = k0; k < k0 + 384; k++) {
                float wk = Wp[k * 32];
                a0 += sdes[0][k] * wk; a1 += sdes[1][k] * wk;
                a2 += sdes[2][k] * wk; a3 += sdes[3][k] * wk;
            }
        } else {
            const float* Wp = Wt + (c - 32);
            #pragma unroll 4
            for (int k = k0; k < k0 + 384; k++) {
                float wk = Wp[k * 32];
                a0 += stw[0][k] * wk; a1 += stw[1][k] * wk;
                a2 += stw[2][k] * wk; a3 += stw[3][k] * wk;
            }
        }
        ps[t][0] = a0; ps[t][1] = a1; ps[t][2] = a2; ps[t][3] = a3;
    }
    __syncthreads();

    if (t < 64) {
        int c = t;
        float bias = (c < 32) ? bd[c] : bt[c - 32];
        #pragma unroll
        for (int m = 0; m < 4; m++) {
            float v = ps[c][m] + ps[c + 64][m] + bias;
            x0[m][c] = lrelu(v);
        }
    } else {
        int c = t - 64;
        if (c < 32) {
            #pragma unroll
            for (int m = 0; m < 4; m++) {
                int node = node0 + m;
                float v = bn[c];
                if (node < n) {
                    const float* xp = nump + (size_t)node * 6;
                    #pragma unroll
                    for (int k = 0; k < 6; k++) v += xp[k] * Wn[k * 32 + c];
                }
                x0[m][64 + c] = lrelu(v);
            }
        } else {
            int cc = c - 32;
            #pragma unroll
            for (int m = 0; m < 4; m++) {
                int node = node0 + m;
                float v = bc[cc];
                if (node < n) {
                    const float* xp = catp + (size_t)node * 11;
                    #pragma unroll
                    for (int k = 0; k < 11; k++) v += xp[k] * Wc[k * 32 + cc];
                }
                x0[m][96 + cc] = lrelu(v);
            }
        }
    }
    __syncthreads();

    {
        float b = bin[t];
        float a0 = b, a1 = b, a2 = b, a3 = b;
        const float* Wp = Win + t;
        #pragma unroll 4
        for (int k = 0; k < 128; k++) {
            float wk = Wp[k * 128];
            a0 += x0[0][k] * wk; a1 += x0[1][k] * wk;
            a2 += x0[2][k] * wk; a3 += x0[3][k] * wk;
        }
        float acc[4] = {a0, a1, a2, a3};
        #pragma unroll
        for (int m = 0; m < 4; m++) {
            int node = node0 + m;
            if (node < n) g_bufA[(size_t)node * 128 + t] = lrelu(acc[m]);
        }
    }
}

// ---------------- 128x128 GEMM: g_bufA @ W -> g_bufB, 16 nodes/block ----------------
__global__ void __launch_bounds__(128) gemm128(const float* __restrict__ W, int n)
{
    __shared__ float xs[16][128];
    int t = threadIdx.x;
    int node0 = blockIdx.x * 16;
    #pragma unroll
    for (int m = 0; m < 16; m++) {
        int nd = node0 + m;
        xs[m][t] = (nd < n) ? g_bufA[(size_t)nd * 128 + t] : 0.0f;
    }
    __syncthreads();

    float acc[16];
    #pragma unroll
    for (int m = 0; m < 16; m++) acc[m] = 0.0f;
    const float* Wp = W + t;
    #pragma unroll 2
    for (int k = 0; k < 128; k++) {
        float wk = Wp[k * 128];
        #pragma unroll
        for (int m = 0; m < 16; m++) acc[m] += xs[m][k] * wk;
    }
    #pragma unroll
    for (int m = 0; m < 16; m++) {
        int nd = node0 + m;
        if (nd < n) g_bufB[(size_t)nd * 128 + t] = acc[m];
    }
}

// ---------------- CSR gather aggregation (fused self-loop + bias) ----------------
// out[d] = dinv[d] * ( dinv[d]*Y[d] + sum_{s in N(d)} dinv[s]*Y[s] ) + bias
// One warp per dst node; float4 per lane.
__global__ void __launch_bounds__(256) gather(const float* __restrict__ bias, int n)
{
    int gid = blockIdx.x * blockDim.x + threadIdx.x;
    int node = gid >> 5;
    int lane = gid & 31;
    if (node >= n) return;

    const float4* Y4 = (const float4*)g_bufB;
    float wd = g_dinv[node];
    float4 y = Y4[(size_t)node * 32 + lane];
    float4 acc;
    acc.x = wd * y.x; acc.y = wd * y.y; acc.z = wd * y.z; acc.w = wd * y.w;

    int lo = g_rowptr[node], hi = g_rowptr[node + 1];
    for (int e = lo; e < hi; e++) {
        int s = g_csrsrc[e];
        float w = g_dinv[s];
        float4 ys = Y4[(size_t)s * 32 + lane];
        acc.x += w * ys.x; acc.y += w * ys.y; acc.z += w * ys.z; acc.w += w * ys.w;
    }
    float4 b4 = ((const float4*)bias)[lane];
    float4 o;
    o.x = wd * acc.x + b4.x; o.y = wd * acc.y + b4.y;
    o.z = wd * acc.z + b4.z; o.w = wd * acc.w + b4.w;
    ((float4*)g_bufA)[(size_t)node * 32 + lane] = o;
}

// ---------------- output head: lrelu(g_bufA@Wo1+bo1) @ Wo2 + bo2, 8 nodes/block ----------------
__global__ void __launch_bounds__(128) kout(
    const float* __restrict__ Wo1, const float* __restrict__ bo1,
    const float* __restrict__ Wo2, const float* __restrict__ bo2,
    float* __restrict__ out, int n)
{
    __shared__ float xs[8][128];
    __shared__ float sa[8][128];
    int t = threadIdx.x;
    int node0 = blockIdx.x * 8;
    #pragma unroll
    for (int m = 0; m < 8; m++) {
        int nd = node0 + m;
        xs[m][t] = (nd < n) ? g_bufA[(size_t)nd * 128 + t] : 0.0f;
    }
    __syncthreads();

    float b = bo1[t];
    float a[8];
    #pragma unroll
    for (int m = 0; m < 8; m++) a[m] = b;
    const float* Wp = Wo1 + t;
    #pragma unroll 2
    for (int k = 0; k < 128; k++) {
        float wk = Wp[k * 128];
        #pragma unroll
        for (int m = 0; m < 8; m++) a[m] += xs[m][k] * wk;
    }
    #pragma unroll
    for (int m = 0; m < 8; m++) sa[m][t] = lrelu(a[m]);
    __syncthreads();

    if (t < 16) {
        int m = t >> 1, c = t & 1;
        float s = bo2[c];
        #pragma unroll 4
        for (int k = 0; k < 128; k++) s += sa[m][k] * Wo2[k * 2 + c];
        int node = node0 + m;
        if (node < n) out[(size_t)node * 2 + c] = s;
    }
}

extern "C" void kernel_launch(void* const* d_in, const int* in_sizes, int n_in,
                              void* d_out, int out_size)
{
    const float* des   = (const float*)d_in[0];
    const float* tweet = (const float*)d_in[1];
    const float* nump  = (const float*)d_in[2];
    const float* catp  = (const float*)d_in[3];
    const void*  eidx  = d_in[4];
    // d_in[5] edge_type: unused by reference
    const float* Wd  = (const float*)d_in[6];  const float* bd  = (const float*)d_in[7];
    const float* Wt  = (const float*)d_in[8];  const float* bt  = (const float*)d_in[9];
    const float* Wn  = (const float*)d_in[10]; const float* bn  = (const float*)d_in[11];
    const float* Wc  = (const float*)d_in[12]; const float* bc  = (const float*)d_in[13];
    const float* Win = (const float*)d_in[14]; const float* bin = (const float*)d_in[15];
    const float* Wg1 = (const float*)d_in[16]; const float* bg1 = (const float*)d_in[17];
    const float* Wg2 = (const float*)d_in[18]; const float* bg2 = (const float*)d_in[19];
    const float* Wo1 = (const float*)d_in[20]; const float* bo1 = (const float*)d_in[21];
    const float* Wo2 = (const float*)d_in[22]; const float* bo2 = (const float*)d_in[23];
    float* out = (float*)d_out;

    int n  = in_sizes[2] / 6;   // num_prop is [N, 6]
    int ne = in_sizes[5];       // edge_type is [E]
    int nb = (n + 1023) / 1024; // scan blocks (<= 128)

    sniff_dtype<<<1, 32>>>((const int*)eidx, n);

    // degrees -> dinv, and CSR build
    deg_zero<<<(n + 255) / 256, 256>>>(n);
    deg_count<<<(ne + 255) / 256, 256>>>(eidx, ne);
    deg_finish<<<(n + 255) / 256, 256>>>(n);
    scan1<<<nb, 256>>>(n);
    scan2<<<1, 128>>>(nb);
    scan3<<<nb, 256>>>(n, ne);
    csr_fill<<<(ne + 255) / 256, 256>>>(eidx, ne);

    // fused input features + W_in -> g_bufA = x1
    kfeat<<<(n + 3) / 4, 128>>>(des, tweet, nump, catp,
                                Wd, bd, Wt, bt, Wn, bn, Wc, bc, Win, bin, n);

    int gather_blocks = (n * 32 + 255) / 256;

    // GCN layer 1
    gemm128<<<(n + 15) / 16, 128>>>(Wg1, n);
    gather<<<gather_blocks, 256>>>(bg1, n);

    // GCN layer 2
    gemm128<<<(n + 15) / 16, 128>>>(Wg2, n);
    gather<<<gather_blocks, 256>>>(bg2, n);

    // output head
    kout<<<(n + 7) / 8, 128>>>(Wo1, bo1, Wo2, bo2, out, n);
}